// round 1
// baseline (speedup 1.0000x reference)
#include <cuda_runtime.h>
#include <cstdint>

#define B_ 16
#define C_ 512
#define N_ 4096   // H*W
#define W_ 64

// Scratch (allocation-free rule: __device__ globals)
__device__ float g_energy[(size_t)B_ * C_ * C_];   // 16 MiB, becomes attention in-place
__device__ float g_mid[(size_t)B_ * C_ * N_];      // 128 MiB, pre-final-softmax output

// ---------------------------------------------------------------------------
// GEMM1 (NT): energy[b,c,d] = sum_n Q[b,c,n] * KV[b,d,n]
// A = Q [C_, N_] row-major, B = KV [C_, N_] row-major (used transposed), K = N_
// 128x128 tile, BK=8, 256 threads, 8x8 microtile.
// ---------------------------------------------------------------------------
__global__ __launch_bounds__(256, 2)
void gemm_nt_kernel(const float* __restrict__ Q, const float* __restrict__ KV)
{
    __shared__ float As[8][128];
    __shared__ float Bs[8][128];

    const int b    = blockIdx.z;
    const int row0 = blockIdx.y * 128;   // c
    const int col0 = blockIdx.x * 128;   // d

    const float* A  = Q  + (size_t)b * C_ * N_;
    const float* Bm = KV + (size_t)b * C_ * N_;
    float*       Cm = g_energy + (size_t)b * C_ * C_;

    const int tid  = threadIdx.x;
    const int lrow = tid >> 1;          // 0..127
    const int lc4  = (tid & 1) * 4;     // 0 or 4
    const int tx   = tid & 15;
    const int ty   = tid >> 4;

    float acc[8][8];
#pragma unroll
    for (int i = 0; i < 8; i++)
#pragma unroll
        for (int j = 0; j < 8; j++) acc[i][j] = 0.f;

    const float* aptr = A  + (size_t)(row0 + lrow) * N_ + lc4;
    const float* bptr = Bm + (size_t)(col0 + lrow) * N_ + lc4;

    for (int k0 = 0; k0 < N_; k0 += 8) {
        const float4 a4 = *(const float4*)(aptr + k0);
        const float4 b4 = *(const float4*)(bptr + k0);
        __syncthreads();
        As[lc4 + 0][lrow] = a4.x; As[lc4 + 1][lrow] = a4.y;
        As[lc4 + 2][lrow] = a4.z; As[lc4 + 3][lrow] = a4.w;
        Bs[lc4 + 0][lrow] = b4.x; Bs[lc4 + 1][lrow] = b4.y;
        Bs[lc4 + 2][lrow] = b4.z; Bs[lc4 + 3][lrow] = b4.w;
        __syncthreads();
#pragma unroll
        for (int k = 0; k < 8; k++) {
            float ar[8], br[8];
            *(float4*)&ar[0] = *(const float4*)&As[k][ty * 8];
            *(float4*)&ar[4] = *(const float4*)&As[k][ty * 8 + 4];
            *(float4*)&br[0] = *(const float4*)&Bs[k][tx * 8];
            *(float4*)&br[4] = *(const float4*)&Bs[k][tx * 8 + 4];
#pragma unroll
            for (int i = 0; i < 8; i++)
#pragma unroll
                for (int j = 0; j < 8; j++)
                    acc[i][j] = fmaf(ar[i], br[j], acc[i][j]);
        }
    }

#pragma unroll
    for (int i = 0; i < 8; i++) {
        float* crow = Cm + (size_t)(row0 + ty * 8 + i) * C_ + col0 + tx * 8;
        *(float4*)(crow)     = make_float4(acc[i][0], acc[i][1], acc[i][2], acc[i][3]);
        *(float4*)(crow + 4) = make_float4(acc[i][4], acc[i][5], acc[i][6], acc[i][7]);
    }
}

// ---------------------------------------------------------------------------
// Softmax over rows of 512, in place on g_energy.
// softmax(rowmax - e) == exp(rowmin(e) - e) / sum  (shift invariance).
// One block of 128 threads per row, float4 per thread.
// ---------------------------------------------------------------------------
__global__ __launch_bounds__(128)
void softmax512_kernel()
{
    __shared__ float red[4];
    float* e = g_energy + (size_t)blockIdx.x * C_;
    const int t = threadIdx.x;

    float4 v = ((const float4*)e)[t];
    float mn = fminf(fminf(v.x, v.y), fminf(v.z, v.w));
#pragma unroll
    for (int o = 16; o; o >>= 1) mn = fminf(mn, __shfl_xor_sync(0xffffffffu, mn, o));
    if ((t & 31) == 0) red[t >> 5] = mn;
    __syncthreads();
    mn = fminf(fminf(red[0], red[1]), fminf(red[2], red[3]));

    float4 w;
    w.x = __expf(mn - v.x); w.y = __expf(mn - v.y);
    w.z = __expf(mn - v.z); w.w = __expf(mn - v.w);
    float s = (w.x + w.y) + (w.z + w.w);
#pragma unroll
    for (int o = 16; o; o >>= 1) s += __shfl_xor_sync(0xffffffffu, s, o);
    __syncthreads();                 // red reuse
    if ((t & 31) == 0) red[t >> 5] = s;
    __syncthreads();
    const float inv = 1.f / (red[0] + red[1] + red[2] + red[3]);

    w.x *= inv; w.y *= inv; w.z *= inv; w.w *= inv;
    ((float4*)e)[t] = w;
}

// ---------------------------------------------------------------------------
// GEMM2 (NN): mid[b,c,n] = sum_d att[b,c,d] * KV[b,d,n]
// A = attention [C_, C_] row-major, B = KV [C_, N_] row-major, K = C_.
// ---------------------------------------------------------------------------
__global__ __launch_bounds__(256, 2)
void gemm_nn_kernel(const float* __restrict__ KV)
{
    __shared__ float As[8][128];
    __shared__ float Bs[8][128];

    const int b    = blockIdx.z;
    const int row0 = blockIdx.y * 128;   // c
    const int col0 = blockIdx.x * 128;   // n

    const float* A  = g_energy + (size_t)b * C_ * C_;
    const float* Bm = KV       + (size_t)b * C_ * N_;
    float*       Cm = g_mid    + (size_t)b * C_ * N_;

    const int tid   = threadIdx.x;
    const int larow = tid >> 1;          // A loader: 0..127
    const int lac4  = (tid & 1) * 4;
    const int lbrow = tid >> 5;          // B loader: 0..7
    const int lbc   = (tid & 31) * 4;    // 0..124
    const int tx    = tid & 15;
    const int ty    = tid >> 4;

    float acc[8][8];
#pragma unroll
    for (int i = 0; i < 8; i++)
#pragma unroll
        for (int j = 0; j < 8; j++) acc[i][j] = 0.f;

    const float* aptr = A  + (size_t)(row0 + larow) * C_ + lac4;
    const float* bptr = Bm + (size_t)lbrow * N_ + col0 + lbc;

    for (int k0 = 0; k0 < C_; k0 += 8) {
        const float4 a4 = *(const float4*)(aptr + k0);
        const float4 b4 = *(const float4*)(bptr + (size_t)k0 * N_);
        __syncthreads();
        As[lac4 + 0][larow] = a4.x; As[lac4 + 1][larow] = a4.y;
        As[lac4 + 2][larow] = a4.z; As[lac4 + 3][larow] = a4.w;
        *(float4*)&Bs[lbrow][lbc] = b4;
        __syncthreads();
#pragma unroll
        for (int k = 0; k < 8; k++) {
            float ar[8], br[8];
            *(float4*)&ar[0] = *(const float4*)&As[k][ty * 8];
            *(float4*)&ar[4] = *(const float4*)&As[k][ty * 8 + 4];
            *(float4*)&br[0] = *(const float4*)&Bs[k][tx * 8];
            *(float4*)&br[4] = *(const float4*)&Bs[k][tx * 8 + 4];
#pragma unroll
            for (int i = 0; i < 8; i++)
#pragma unroll
                for (int j = 0; j < 8; j++)
                    acc[i][j] = fmaf(ar[i], br[j], acc[i][j]);
        }
    }

#pragma unroll
    for (int i = 0; i < 8; i++) {
        float* crow = Cm + (size_t)(row0 + ty * 8 + i) * N_ + col0 + tx * 8;
        *(float4*)(crow)     = make_float4(acc[i][0], acc[i][1], acc[i][2], acc[i][3]);
        *(float4*)(crow + 4) = make_float4(acc[i][4], acc[i][5], acc[i][6], acc[i][7]);
    }
}

// ---------------------------------------------------------------------------
// Final softmax over W=64 segments. One warp per segment, 2 elems/lane.
// ---------------------------------------------------------------------------
__global__ __launch_bounds__(256)
void softmax64_kernel(float* __restrict__ out)
{
    const int seg  = blockIdx.x * 8 + (threadIdx.x >> 5);
    const int lane = threadIdx.x & 31;

    const float* p = g_mid + (size_t)seg * W_;
    const float a = p[lane];
    const float b = p[lane + 32];

    float m = fmaxf(a, b);
#pragma unroll
    for (int o = 16; o; o >>= 1) m = fmaxf(m, __shfl_xor_sync(0xffffffffu, m, o));

    const float ea = __expf(a - m);
    const float eb = __expf(b - m);
    float s = ea + eb;
#pragma unroll
    for (int o = 16; o; o >>= 1) s += __shfl_xor_sync(0xffffffffu, s, o);
    const float inv = 1.f / s;

    float* q = out + (size_t)seg * W_;
    q[lane]      = ea * inv;
    q[lane + 32] = eb * inv;
}

// ---------------------------------------------------------------------------
extern "C" void kernel_launch(void* const* d_in, const int* in_sizes, int n_in,
                              void* d_out, int out_size)
{
    const float* x_training = (const float*)d_in[0];  // KV (key/value)
    const float* x_pre      = (const float*)d_in[1];  // Q  (query)
    float* out = (float*)d_out;

    // 1) energy = Q @ KV^T  (per batch)
    gemm_nt_kernel<<<dim3(C_ / 128, C_ / 128, B_), 256>>>(x_pre, x_training);

    // 2) attention = softmax(rowmax - energy) over rows of 512 (in place)
    softmax512_kernel<<<B_ * C_, 128>>>();

    // 3) mid = attention @ KV  (per batch)
    gemm_nn_kernel<<<dim3(N_ / 128, C_ / 128, B_), 256>>>(x_training);

    // 4) final softmax over each 64-wide row segment
    const int nseg = B_ * C_ * W_;      // 524288 segments of 64
    softmax64_kernel<<<nseg / 8, 256>>>(out);
}

// round 3
// speedup vs baseline: 2.5980x; 2.5980x over previous
#include <cuda_runtime.h>
#include <cuda_fp16.h>
#include <cstdint>

#define B_ 16
#define C_ 512
#define N_ 4096   // H*W
#define W_ 64

// ---------------- scratch (__device__ globals: allocation-free rule) --------
__device__ __half g_qh[(size_t)B_ * C_ * N_];   // 67 MB each
__device__ __half g_ql[(size_t)B_ * C_ * N_];
__device__ __half g_kh[(size_t)B_ * C_ * N_];
__device__ __half g_kl[(size_t)B_ * C_ * N_];
__device__ __half g_ah[(size_t)B_ * C_ * C_];   // attention hi/lo, 8.4 MB each
__device__ __half g_al[(size_t)B_ * C_ * C_];
__device__ float  g_energy[(size_t)B_ * C_ * C_];

// ---------------- plain-target PTX helpers ----------------------------------
__device__ __forceinline__ uint32_t smem_u32(const void* p) {
    uint32_t a;
    asm("{ .reg .u64 t; cvta.to.shared.u64 t, %1; cvt.u32.u64 %0, t; }" : "=r"(a) : "l"(p));
    return a;
}
__device__ __forceinline__ void ldsm4(uint32_t* r, uint32_t addr) {
    asm volatile("ldmatrix.sync.aligned.m8n8.x4.shared.b16 {%0,%1,%2,%3}, [%4];"
                 : "=r"(r[0]), "=r"(r[1]), "=r"(r[2]), "=r"(r[3]) : "r"(addr));
}
__device__ __forceinline__ void ldsm4t(uint32_t* r, uint32_t addr) {
    asm volatile("ldmatrix.sync.aligned.m8n8.x4.trans.shared.b16 {%0,%1,%2,%3}, [%4];"
                 : "=r"(r[0]), "=r"(r[1]), "=r"(r[2]), "=r"(r[3]) : "r"(addr));
}
__device__ __forceinline__ void mma16816(float* d, const uint32_t* a, const uint32_t* b) {
    asm volatile(
        "mma.sync.aligned.m16n8k16.row.col.f32.f16.f16.f32 "
        "{%0,%1,%2,%3}, {%4,%5,%6,%7}, {%8,%9}, {%0,%1,%2,%3};"
        : "+f"(d[0]), "+f"(d[1]), "+f"(d[2]), "+f"(d[3])
        : "r"(a[0]), "r"(a[1]), "r"(a[2]), "r"(a[3]), "r"(b[0]), "r"(b[1]));
}
#define CP_ASYNC16(s, g) \
    asm volatile("cp.async.cg.shared.global [%0], [%1], 16;" :: "r"(s), "l"(g))
#define CP_COMMIT()  asm volatile("cp.async.commit_group;" ::: "memory")
#define CP_WAIT1()   asm volatile("cp.async.wait_group 1;" ::: "memory")

// Swizzled byte offsets inside an 8 KB tile.
// A-type tile: 128 rows x 32 halves (64 B/row); chunk = 16 B.
__device__ __forceinline__ uint32_t offA(int row, int ch) {
    return row * 64 + ((ch ^ ((row >> 1) & 3)) * 16);
}
// B-type tile (n-major): 32 rows x 128 halves (256 B/row).
__device__ __forceinline__ uint32_t offB(int krow, int ch) {
    return krow * 256 + ((ch ^ (krow & 7)) * 16);
}

// ---------------- prep: fp16 hi/lo split ------------------------------------
__global__ __launch_bounds__(256)
void split_kernel(const float* __restrict__ x, __half* __restrict__ hi, __half* __restrict__ lo)
{
    const size_t i = (size_t)blockIdx.x * 256 + threadIdx.x;
    const float4 v = ((const float4*)x)[i];
    const __half h0 = __float2half(v.x), h1 = __float2half(v.y);
    const __half h2 = __float2half(v.z), h3 = __float2half(v.w);
    const __half l0 = __float2half(v.x - __half2float(h0));
    const __half l1 = __float2half(v.y - __half2float(h1));
    const __half l2 = __float2half(v.z - __half2float(h2));
    const __half l3 = __float2half(v.w - __half2float(h3));
    ((__half2*)hi)[2 * i]     = __halves2half2(h0, h1);
    ((__half2*)hi)[2 * i + 1] = __halves2half2(h2, h3);
    ((__half2*)lo)[2 * i]     = __halves2half2(l0, l1);
    ((__half2*)lo)[2 * i + 1] = __halves2half2(l2, l3);
}

// ---------------- GEMM1 (NT): energy[c,d] = sum_n q[c,n] kv[d,n] -----------
// fp16 split operands, fp32 acc, 3 products (hh + hl + lh).
// 128x128 tile, BK=32, cp.async double buffer, warps 2x4 (64x32 each).
__global__ __launch_bounds__(256, 1)
void gemm1_kernel(const __half* __restrict__ Ah, const __half* __restrict__ Al,
                  const __half* __restrict__ Bh, const __half* __restrict__ Bl)
{
    extern __shared__ char smem[];
    const uint32_t sb = smem_u32(smem);
    const int tid = threadIdx.x, wid = tid >> 5, lane = tid & 31;
    const int b = blockIdx.z, row0 = blockIdx.y * 128, col0 = blockIdx.x * 128;
    const size_t bstr = (size_t)b * C_ * N_;

    const __half* srcs[4] = {
        Ah + bstr + (size_t)row0 * N_, Al + bstr + (size_t)row0 * N_,
        Bh + bstr + (size_t)col0 * N_, Bl + bstr + (size_t)col0 * N_ };

    auto load_stage = [&](int kb, int stage) {
        const uint32_t st = sb + stage * 32768;
#pragma unroll
        for (int t = 0; t < 4; t++) {
            const __half* src = srcs[t] + kb * 32;
            const uint32_t tb = st + t * 8192;
#pragma unroll
            for (int i = 0; i < 2; i++) {
                const int idx = tid + i * 256;
                const int row = idx >> 2, ch = idx & 3;
                CP_ASYNC16(tb + offA(row, ch), src + (size_t)row * N_ + ch * 8);
            }
        }
    };

    float acc[4][4][4];
#pragma unroll
    for (int i = 0; i < 4; i++)
#pragma unroll
        for (int j = 0; j < 4; j++)
#pragma unroll
            for (int k = 0; k < 4; k++) acc[i][j][k] = 0.f;

    load_stage(0, 0); CP_COMMIT();
    load_stage(1, 1); CP_COMMIT();

    const int wm = wid >> 2, wn = wid & 3;
    constexpr int NKB = N_ / 32;   // 128

    for (int kb = 0; kb < NKB; kb++) {
        CP_WAIT1();
        __syncthreads();
        const uint32_t sAh = sb + (kb & 1) * 32768;
        const uint32_t sAl = sAh + 8192, sBh = sAh + 16384, sBl = sAh + 24576;
#pragma unroll
        for (int ks = 0; ks < 2; ks++) {
            uint32_t afh[4][4], afl[4][4];
            {
                const int rb = wm * 64 + (lane & 7) + ((lane >> 3) & 1) * 8;
                const int ch = ks * 2 + (lane >> 4);
#pragma unroll
                for (int mt = 0; mt < 4; mt++) {
                    const uint32_t o = offA(rb + mt * 16, ch);
                    ldsm4(afh[mt], sAh + o);
                    ldsm4(afl[mt], sAl + o);
                }
            }
#pragma unroll
            for (int nt2 = 0; nt2 < 2; nt2++) {
                const int rb = wn * 32 + nt2 * 16 + (lane & 7) + ((lane >> 4) & 1) * 8;
                const int ch = ks * 2 + ((lane >> 3) & 1);
                const uint32_t o = offA(rb, ch);
                uint32_t bfh[4], bfl[4];
                ldsm4(bfh, sBh + o);
                ldsm4(bfl, sBl + o);
#pragma unroll
                for (int mt = 0; mt < 4; mt++) {
                    mma16816(acc[mt][nt2 * 2],     afh[mt], bfh);
                    mma16816(acc[mt][nt2 * 2 + 1], afh[mt], bfh + 2);
                    mma16816(acc[mt][nt2 * 2],     afh[mt], bfl);
                    mma16816(acc[mt][nt2 * 2 + 1], afh[mt], bfl + 2);
                    mma16816(acc[mt][nt2 * 2],     afl[mt], bfh);
                    mma16816(acc[mt][nt2 * 2 + 1], afl[mt], bfh + 2);
                }
            }
        }
        __syncthreads();
        if (kb + 2 < NKB) load_stage(kb + 2, kb & 1);
        CP_COMMIT();
    }

    // epilogue: plain fp32 store to g_energy
    float* Cm = g_energy + (size_t)b * C_ * C_;
    const int r0 = row0 + wm * 64 + (lane >> 2);
    const int c0g = col0 + wn * 32 + (lane & 3) * 2;
#pragma unroll
    for (int mt = 0; mt < 4; mt++)
#pragma unroll
        for (int nt = 0; nt < 4; nt++) {
            float* p = Cm + (size_t)(r0 + mt * 16) * C_ + c0g + nt * 8;
            *(float2*)p = make_float2(acc[mt][nt][0], acc[mt][nt][1]);
            *(float2*)(p + 8 * C_) = make_float2(acc[mt][nt][2], acc[mt][nt][3]);
        }
}

// ---------------- softmax over 512 + fp16 split of attention ---------------
__global__ __launch_bounds__(128)
void softmax512_split_kernel()
{
    __shared__ float red[4];
    const size_t row = blockIdx.x;
    const float* e = g_energy + row * C_;
    const int t = threadIdx.x;

    float4 v = ((const float4*)e)[t];
    float mn = fminf(fminf(v.x, v.y), fminf(v.z, v.w));
#pragma unroll
    for (int o = 16; o; o >>= 1) mn = fminf(mn, __shfl_xor_sync(0xffffffffu, mn, o));
    if ((t & 31) == 0) red[t >> 5] = mn;
    __syncthreads();
    mn = fminf(fminf(red[0], red[1]), fminf(red[2], red[3]));

    float4 w;
    w.x = __expf(mn - v.x); w.y = __expf(mn - v.y);
    w.z = __expf(mn - v.z); w.w = __expf(mn - v.w);
    float s = (w.x + w.y) + (w.z + w.w);
#pragma unroll
    for (int o = 16; o; o >>= 1) s += __shfl_xor_sync(0xffffffffu, s, o);
    __syncthreads();
    if ((t & 31) == 0) red[t >> 5] = s;
    __syncthreads();
    const float inv = 1.f / (red[0] + red[1] + red[2] + red[3]);
    w.x *= inv; w.y *= inv; w.z *= inv; w.w *= inv;

    const __half h0 = __float2half(w.x), h1 = __float2half(w.y);
    const __half h2 = __float2half(w.z), h3 = __float2half(w.w);
    const __half l0 = __float2half(w.x - __half2float(h0));
    const __half l1 = __float2half(w.y - __half2float(h1));
    const __half l2 = __float2half(w.z - __half2float(h2));
    const __half l3 = __float2half(w.w - __half2float(h3));
    __half2* ah = (__half2*)(g_ah + row * C_);
    __half2* al = (__half2*)(g_al + row * C_);
    ah[2 * t]     = __halves2half2(h0, h1);
    ah[2 * t + 1] = __halves2half2(h2, h3);
    al[2 * t]     = __halves2half2(l0, l1);
    al[2 * t + 1] = __halves2half2(l2, l3);
}

// ---------------- GEMM2 (NN): out[c,n] = softmax64( sum_d att[c,d] kv[d,n] )
// A = attention [C,C] (k contig), B = kv [C,N] (n contig, trans-ldmatrix).
// 128x128 tile, BK=32, warps 8x1 (16 rows x 128 cols each), fused softmax.
__global__ __launch_bounds__(256, 1)
void gemm2_kernel(const __half* __restrict__ Bh, const __half* __restrict__ Bl,
                  float* __restrict__ Out)
{
    extern __shared__ char smem[];
    const uint32_t sb = smem_u32(smem);
    const int tid = threadIdx.x, wid = tid >> 5, lane = tid & 31;
    const int b = blockIdx.z, row0 = blockIdx.y * 128, col0 = blockIdx.x * 128;

    const __half* aSrcs[2] = {
        g_ah + (size_t)b * C_ * C_ + (size_t)row0 * C_,
        g_al + (size_t)b * C_ * C_ + (size_t)row0 * C_ };
    const __half* bSrcs[2] = {
        Bh + (size_t)b * C_ * N_ + col0,
        Bl + (size_t)b * C_ * N_ + col0 };

    auto load_stage = [&](int kb, int stage) {
        const uint32_t st = sb + stage * 32768;
#pragma unroll
        for (int t = 0; t < 2; t++) {         // A tiles (A-type layout)
            const __half* src = aSrcs[t] + kb * 32;
            const uint32_t tb = st + t * 8192;
#pragma unroll
            for (int i = 0; i < 2; i++) {
                const int idx = tid + i * 256;
                const int row = idx >> 2, ch = idx & 3;
                CP_ASYNC16(tb + offA(row, ch), src + (size_t)row * C_ + ch * 8);
            }
        }
#pragma unroll
        for (int t = 0; t < 2; t++) {         // B tiles (n-major layout)
            const __half* src = bSrcs[t] + (size_t)(kb * 32) * N_;
            const uint32_t tb = st + 16384 + t * 8192;
#pragma unroll
            for (int i = 0; i < 2; i++) {
                const int idx = tid + i * 256;
                const int krow = idx >> 4, ch = idx & 15;
                CP_ASYNC16(tb + offB(krow, ch), src + (size_t)krow * N_ + ch * 8);
            }
        }
    };

    float acc[16][4];
#pragma unroll
    for (int i = 0; i < 16; i++)
#pragma unroll
        for (int k = 0; k < 4; k++) acc[i][k] = 0.f;

    load_stage(0, 0); CP_COMMIT();
    load_stage(1, 1); CP_COMMIT();

    constexpr int NKB = C_ / 32;   // 16

    for (int kb = 0; kb < NKB; kb++) {
        CP_WAIT1();
        __syncthreads();
        const uint32_t sAh = sb + (kb & 1) * 32768;
        const uint32_t sAl = sAh + 8192, sBh = sAh + 16384, sBl = sAh + 24576;
#pragma unroll
        for (int ks = 0; ks < 2; ks++) {
            uint32_t afh[4], afl[4];
            {
                const int row = wid * 16 + (lane & 7) + ((lane >> 3) & 1) * 8;
                const int ch = ks * 2 + (lane >> 4);
                const uint32_t o = offA(row, ch);
                ldsm4(afh, sAh + o);
                ldsm4(afl, sAl + o);
            }
            const int krow = ks * 16 + (lane & 7) + ((lane >> 3) & 1) * 8;
#pragma unroll
            for (int nt2 = 0; nt2 < 8; nt2++) {
                const int ch = nt2 * 2 + (lane >> 4);
                const uint32_t o = offB(krow, ch);
                uint32_t bfh[4], bfl[4];
                ldsm4t(bfh, sBh + o);
                ldsm4t(bfl, sBl + o);
                mma16816(acc[nt2 * 2],     afh, bfh);
                mma16816(acc[nt2 * 2 + 1], afh, bfh + 2);
                mma16816(acc[nt2 * 2],     afh, bfl);
                mma16816(acc[nt2 * 2 + 1], afh, bfl + 2);
                mma16816(acc[nt2 * 2],     afl, bfh);
                mma16816(acc[nt2 * 2 + 1], afl, bfh + 2);
            }
        }
        __syncthreads();
        if (kb + 2 < NKB) load_stage(kb + 2, kb & 1);
        CP_COMMIT();
    }

    // epilogue: fused softmax over each 64-wide segment (2 per tile).
    // thread owns rows r, r+8; per row 2 cols in each of 16 n-tiles.
    const int rloc = wid * 16 + (lane >> 2);
#pragma unroll
    for (int h = 0; h < 2; h++) {            // row half: acc[..][2h],[2h+1]
        const int r = rloc + h * 8;
        float* orow = Out + ((size_t)b * C_ + row0 + r) * N_ + col0;
#pragma unroll
        for (int seg = 0; seg < 2; seg++) {
            float v[16];
#pragma unroll
            for (int j = 0; j < 8; j++) {
                v[2 * j]     = acc[seg * 8 + j][2 * h];
                v[2 * j + 1] = acc[seg * 8 + j][2 * h + 1];
            }
            float m = v[0];
#pragma unroll
            for (int j = 1; j < 16; j++) m = fmaxf(m, v[j]);
            m = fmaxf(m, __shfl_xor_sync(0xffffffffu, m, 1));
            m = fmaxf(m, __shfl_xor_sync(0xffffffffu, m, 2));
            float s = 0.f;
#pragma unroll
            for (int j = 0; j < 16; j++) { v[j] = __expf(v[j] - m); s += v[j]; }
            s += __shfl_xor_sync(0xffffffffu, s, 1);
            s += __shfl_xor_sync(0xffffffffu, s, 2);
            const float inv = 1.f / s;
#pragma unroll
            for (int j = 0; j < 8; j++) {
                float* p = orow + seg * 64 + j * 8 + (lane & 3) * 2;
                *(float2*)p = make_float2(v[2 * j] * inv, v[2 * j + 1] * inv);
            }
        }
    }
}

// ---------------------------------------------------------------------------
extern "C" void kernel_launch(void* const* d_in, const int* in_sizes, int n_in,
                              void* d_out, int out_size)
{
    const float* x_training = (const float*)d_in[0];  // KV
    const float* x_pre      = (const float*)d_in[1];  // Q
    float* out = (float*)d_out;

    cudaFuncSetAttribute(gemm1_kernel, cudaFuncAttributeMaxDynamicSharedMemorySize, 65536);
    cudaFuncSetAttribute(gemm2_kernel, cudaFuncAttributeMaxDynamicSharedMemorySize, 65536);

    __half *qh, *ql, *kh, *kl;
    cudaGetSymbolAddress((void**)&qh, g_qh);
    cudaGetSymbolAddress((void**)&ql, g_ql);
    cudaGetSymbolAddress((void**)&kh, g_kh);
    cudaGetSymbolAddress((void**)&kl, g_kl);

    const int nvec = B_ * C_ * N_ / 4;    // float4s per tensor

    // 1) fp16 hi/lo splits (KV split serves both GEMMs)
    split_kernel<<<nvec / 256, 256>>>(x_pre, qh, ql);
    split_kernel<<<nvec / 256, 256>>>(x_training, kh, kl);
    // 2) energy = Q @ KV^T   (HMMA, fp16-split 3-product)
    gemm1_kernel<<<dim3(C_ / 128, C_ / 128, B_), 256, 65536>>>(qh, ql, kh, kl);
    // 3) attention = softmax(min - energy), split to fp16 hi/lo
    softmax512_split_kernel<<<B_ * C_, 128>>>();
    // 4) out = softmax64(attention @ KV)   (HMMA + fused final softmax)
    gemm2_kernel<<<dim3(N_ / 128, C_ / 128, B_), 256, 65536>>>(kh, kl, out);
}

// round 4
// speedup vs baseline: 2.6185x; 1.0079x over previous
#include <cuda_runtime.h>
#include <cuda_fp16.h>
#include <cstdint>

#define B_ 16
#define C_ 512
#define N_ 4096   // H*W
#define W_ 64

// ---------------- scratch (__device__ globals: allocation-free rule) --------
__device__ __half g_qh[(size_t)B_ * C_ * N_];   // 67 MB each
__device__ __half g_ql[(size_t)B_ * C_ * N_];
__device__ __half g_kh[(size_t)B_ * C_ * N_];
__device__ __half g_kl[(size_t)B_ * C_ * N_];
__device__ __half g_ah[(size_t)B_ * C_ * C_];   // attention hi/lo, 8.4 MB each
__device__ __half g_al[(size_t)B_ * C_ * C_];
__device__ float  g_energy[(size_t)B_ * C_ * C_];

// ---------------- plain-target PTX helpers ----------------------------------
__device__ __forceinline__ uint32_t smem_u32(const void* p) {
    uint32_t a;
    asm("{ .reg .u64 t; cvta.to.shared.u64 t, %1; cvt.u32.u64 %0, t; }" : "=r"(a) : "l"(p));
    return a;
}
__device__ __forceinline__ void ldsm4(uint32_t* r, uint32_t addr) {
    asm volatile("ldmatrix.sync.aligned.m8n8.x4.shared.b16 {%0,%1,%2,%3}, [%4];"
                 : "=r"(r[0]), "=r"(r[1]), "=r"(r[2]), "=r"(r[3]) : "r"(addr));
}
__device__ __forceinline__ void ldsm4t(uint32_t* r, uint32_t addr) {
    asm volatile("ldmatrix.sync.aligned.m8n8.x4.trans.shared.b16 {%0,%1,%2,%3}, [%4];"
                 : "=r"(r[0]), "=r"(r[1]), "=r"(r[2]), "=r"(r[3]) : "r"(addr));
}
__device__ __forceinline__ void mma16816(float* d, const uint32_t* a, const uint32_t* b) {
    asm volatile(
        "mma.sync.aligned.m16n8k16.row.col.f32.f16.f16.f32 "
        "{%0,%1,%2,%3}, {%4,%5,%6,%7}, {%8,%9}, {%0,%1,%2,%3};"
        : "+f"(d[0]), "+f"(d[1]), "+f"(d[2]), "+f"(d[3])
        : "r"(a[0]), "r"(a[1]), "r"(a[2]), "r"(a[3]), "r"(b[0]), "r"(b[1]));
}
#define CP_ASYNC16(s, g) \
    asm volatile("cp.async.cg.shared.global [%0], [%1], 16;" :: "r"(s), "l"(g))
#define CP_COMMIT()  asm volatile("cp.async.commit_group;" ::: "memory")
#define CP_WAIT2()   asm volatile("cp.async.wait_group 2;" ::: "memory")

// Swizzled byte offsets inside an 8 KB tile.
// A-type tile: 128 rows x 32 halves (64 B/row); chunk = 16 B.
__device__ __forceinline__ uint32_t offA(int row, int ch) {
    return row * 64 + ((ch ^ ((row >> 1) & 3)) * 16);
}
// B-type tile (n-major): 32 rows x 128 halves (256 B/row).
__device__ __forceinline__ uint32_t offB(int krow, int ch) {
    return krow * 256 + ((ch ^ (krow & 7)) * 16);
}

static constexpr int STAGES   = 4;
static constexpr int STAGE_SZ = 32768;
static constexpr int SMEM_SZ  = STAGES * STAGE_SZ;   // 128 KB

// ---------------- prep: fp16 hi/lo split ------------------------------------
__global__ __launch_bounds__(256)
void split_kernel(const float* __restrict__ x, __half* __restrict__ hi, __half* __restrict__ lo)
{
    const size_t i = (size_t)blockIdx.x * 256 + threadIdx.x;
    const float4 v = ((const float4*)x)[i];
    const __half h0 = __float2half(v.x), h1 = __float2half(v.y);
    const __half h2 = __float2half(v.z), h3 = __float2half(v.w);
    const __half l0 = __float2half(v.x - __half2float(h0));
    const __half l1 = __float2half(v.y - __half2float(h1));
    const __half l2 = __float2half(v.z - __half2float(h2));
    const __half l3 = __float2half(v.w - __half2float(h3));
    ((__half2*)hi)[2 * i]     = __halves2half2(h0, h1);
    ((__half2*)hi)[2 * i + 1] = __halves2half2(h2, h3);
    ((__half2*)lo)[2 * i]     = __halves2half2(l0, l1);
    ((__half2*)lo)[2 * i + 1] = __halves2half2(l2, l3);
}

// ---------------- GEMM1 (NT): energy[c,d] = sum_n q[c,n] kv[d,n] -----------
// fp16 split operands, fp32 acc, 3 products (hh + hl + lh).
// 128x128 tile, BK=32, 4-stage cp.async pipeline, one sync per K-block.
__global__ __launch_bounds__(256, 1)
void gemm1_kernel(const __half* __restrict__ Ah, const __half* __restrict__ Al,
                  const __half* __restrict__ Bh, const __half* __restrict__ Bl)
{
    extern __shared__ char smem[];
    const uint32_t sb = smem_u32(smem);
    const int tid = threadIdx.x, wid = tid >> 5, lane = tid & 31;
    const int b = blockIdx.z, row0 = blockIdx.y * 128, col0 = blockIdx.x * 128;
    const size_t bstr = (size_t)b * C_ * N_;

    const __half* srcs[4] = {
        Ah + bstr + (size_t)row0 * N_, Al + bstr + (size_t)row0 * N_,
        Bh + bstr + (size_t)col0 * N_, Bl + bstr + (size_t)col0 * N_ };

    auto load_stage = [&](int kb) {
        const uint32_t st = sb + (kb % STAGES) * STAGE_SZ;
#pragma unroll
        for (int t = 0; t < 4; t++) {
            const __half* src = srcs[t] + kb * 32;
            const uint32_t tb = st + t * 8192;
#pragma unroll
            for (int i = 0; i < 2; i++) {
                const int idx = tid + i * 256;
                const int row = idx >> 2, ch = idx & 3;
                CP_ASYNC16(tb + offA(row, ch), src + (size_t)row * N_ + ch * 8);
            }
        }
    };

    float acc[4][4][4];
#pragma unroll
    for (int i = 0; i < 4; i++)
#pragma unroll
        for (int j = 0; j < 4; j++)
#pragma unroll
            for (int k = 0; k < 4; k++) acc[i][j][k] = 0.f;

    load_stage(0); CP_COMMIT();
    load_stage(1); CP_COMMIT();
    load_stage(2); CP_COMMIT();

    const int wm = wid >> 2, wn = wid & 3;
    constexpr int NKB = N_ / 32;   // 128

    for (int kb = 0; kb < NKB; kb++) {
        CP_WAIT2();
        __syncthreads();
        if (kb + 3 < NKB) load_stage(kb + 3);
        CP_COMMIT();
        const uint32_t sAh = sb + (kb % STAGES) * STAGE_SZ;
        const uint32_t sAl = sAh + 8192, sBh = sAh + 16384, sBl = sAh + 24576;
#pragma unroll
        for (int ks = 0; ks < 2; ks++) {
            uint32_t afh[4][4], afl[4][4];
            {
                const int rb = wm * 64 + (lane & 7) + ((lane >> 3) & 1) * 8;
                const int ch = ks * 2 + (lane >> 4);
#pragma unroll
                for (int mt = 0; mt < 4; mt++) {
                    const uint32_t o = offA(rb + mt * 16, ch);
                    ldsm4(afh[mt], sAh + o);
                    ldsm4(afl[mt], sAl + o);
                }
            }
#pragma unroll
            for (int nt2 = 0; nt2 < 2; nt2++) {
                const int rb = wn * 32 + nt2 * 16 + (lane & 7) + ((lane >> 4) & 1) * 8;
                const int ch = ks * 2 + ((lane >> 3) & 1);
                const uint32_t o = offA(rb, ch);
                uint32_t bfh[4], bfl[4];
                ldsm4(bfh, sBh + o);
                ldsm4(bfl, sBl + o);
#pragma unroll
                for (int mt = 0; mt < 4; mt++) {
                    mma16816(acc[mt][nt2 * 2],     afh[mt], bfh);
                    mma16816(acc[mt][nt2 * 2 + 1], afh[mt], bfh + 2);
                    mma16816(acc[mt][nt2 * 2],     afh[mt], bfl);
                    mma16816(acc[mt][nt2 * 2 + 1], afh[mt], bfl + 2);
                    mma16816(acc[mt][nt2 * 2],     afl[mt], bfh);
                    mma16816(acc[mt][nt2 * 2 + 1], afl[mt], bfh + 2);
                }
            }
        }
    }

    // epilogue: plain fp32 store to g_energy
    float* Cm = g_energy + (size_t)b * C_ * C_;
    const int r0 = row0 + wm * 64 + (lane >> 2);
    const int c0g = col0 + wn * 32 + (lane & 3) * 2;
#pragma unroll
    for (int mt = 0; mt < 4; mt++)
#pragma unroll
        for (int nt = 0; nt < 4; nt++) {
            float* p = Cm + (size_t)(r0 + mt * 16) * C_ + c0g + nt * 8;
            *(float2*)p = make_float2(acc[mt][nt][0], acc[mt][nt][1]);
            *(float2*)(p + 8 * C_) = make_float2(acc[mt][nt][2], acc[mt][nt][3]);
        }
}

// ---------------- softmax over 512 + fp16 split of attention ---------------
__global__ __launch_bounds__(128)
void softmax512_split_kernel()
{
    __shared__ float red[4];
    const size_t row = blockIdx.x;
    const float* e = g_energy + row * C_;
    const int t = threadIdx.x;

    float4 v = ((const float4*)e)[t];
    float mn = fminf(fminf(v.x, v.y), fminf(v.z, v.w));
#pragma unroll
    for (int o = 16; o; o >>= 1) mn = fminf(mn, __shfl_xor_sync(0xffffffffu, mn, o));
    if ((t & 31) == 0) red[t >> 5] = mn;
    __syncthreads();
    mn = fminf(fminf(red[0], red[1]), fminf(red[2], red[3]));

    float4 w;
    w.x = __expf(mn - v.x); w.y = __expf(mn - v.y);
    w.z = __expf(mn - v.z); w.w = __expf(mn - v.w);
    float s = (w.x + w.y) + (w.z + w.w);
#pragma unroll
    for (int o = 16; o; o >>= 1) s += __shfl_xor_sync(0xffffffffu, s, o);
    __syncthreads();
    if ((t & 31) == 0) red[t >> 5] = s;
    __syncthreads();
    const float inv = 1.f / (red[0] + red[1] + red[2] + red[3]);
    w.x *= inv; w.y *= inv; w.z *= inv; w.w *= inv;

    const __half h0 = __float2half(w.x), h1 = __float2half(w.y);
    const __half h2 = __float2half(w.z), h3 = __float2half(w.w);
    const __half l0 = __float2half(w.x - __half2float(h0));
    const __half l1 = __float2half(w.y - __half2float(h1));
    const __half l2 = __float2half(w.z - __half2float(h2));
    const __half l3 = __float2half(w.w - __half2float(h3));
    __half2* ah = (__half2*)(g_ah + row * C_);
    __half2* al = (__half2*)(g_al + row * C_);
    ah[2 * t]     = __halves2half2(h0, h1);
    ah[2 * t + 1] = __halves2half2(h2, h3);
    al[2 * t]     = __halves2half2(l0, l1);
    al[2 * t + 1] = __halves2half2(l2, l3);
}

// ---------------- GEMM2 (NN): out[c,n] = softmax64( sum_d att[c,d] kv[d,n] )
// A = attention [C,C] (k contig), B = kv [C,N] (n contig, trans-ldmatrix).
// 128x128 tile, BK=32, warps 8x1 (16 rows x 128 cols each), fused softmax.
__global__ __launch_bounds__(256, 1)
void gemm2_kernel(const __half* __restrict__ Bh, const __half* __restrict__ Bl,
                  float* __restrict__ Out)
{
    extern __shared__ char smem[];
    const uint32_t sb = smem_u32(smem);
    const int tid = threadIdx.x, wid = tid >> 5, lane = tid & 31;
    const int b = blockIdx.z, row0 = blockIdx.y * 128, col0 = blockIdx.x * 128;

    const __half* aSrcs[2] = {
        g_ah + (size_t)b * C_ * C_ + (size_t)row0 * C_,
        g_al + (size_t)b * C_ * C_ + (size_t)row0 * C_ };
    const __half* bSrcs[2] = {
        Bh + (size_t)b * C_ * N_ + col0,
        Bl + (size_t)b * C_ * N_ + col0 };

    auto load_stage = [&](int kb) {
        const uint32_t st = sb + (kb % STAGES) * STAGE_SZ;
#pragma unroll
        for (int t = 0; t < 2; t++) {         // A tiles (A-type layout)
            const __half* src = aSrcs[t] + kb * 32;
            const uint32_t tb = st + t * 8192;
#pragma unroll
            for (int i = 0; i < 2; i++) {
                const int idx = tid + i * 256;
                const int row = idx >> 2, ch = idx & 3;
                CP_ASYNC16(tb + offA(row, ch), src + (size_t)row * C_ + ch * 8);
            }
        }
#pragma unroll
        for (int t = 0; t < 2; t++) {         // B tiles (n-major layout)
            const __half* src = bSrcs[t] + (size_t)(kb * 32) * N_;
            const uint32_t tb = st + 16384 + t * 8192;
#pragma unroll
            for (int i = 0; i < 2; i++) {
                const int idx = tid + i * 256;
                const int krow = idx >> 4, ch = idx & 15;
                CP_ASYNC16(tb + offB(krow, ch), src + (size_t)krow * N_ + ch * 8);
            }
        }
    };

    float acc[16][4];
#pragma unroll
    for (int i = 0; i < 16; i++)
#pragma unroll
        for (int k = 0; k < 4; k++) acc[i][k] = 0.f;

    load_stage(0); CP_COMMIT();
    load_stage(1); CP_COMMIT();
    load_stage(2); CP_COMMIT();

    constexpr int NKB = C_ / 32;   // 16

    for (int kb = 0; kb < NKB; kb++) {
        CP_WAIT2();
        __syncthreads();
        if (kb + 3 < NKB) load_stage(kb + 3);
        CP_COMMIT();
        const uint32_t sAh = sb + (kb % STAGES) * STAGE_SZ;
        const uint32_t sAl = sAh + 8192, sBh = sAh + 16384, sBl = sAh + 24576;
#pragma unroll
        for (int ks = 0; ks < 2; ks++) {
            uint32_t afh[4], afl[4];
            {
                const int row = wid * 16 + (lane & 7) + ((lane >> 3) & 1) * 8;
                const int ch = ks * 2 + (lane >> 4);
                const uint32_t o = offA(row, ch);
                ldsm4(afh, sAh + o);
                ldsm4(afl, sAl + o);
            }
            const int krow = ks * 16 + (lane & 7) + ((lane >> 3) & 1) * 8;
#pragma unroll
            for (int nt2 = 0; nt2 < 8; nt2++) {
                const int ch = nt2 * 2 + (lane >> 4);
                const uint32_t o = offB(krow, ch);
                uint32_t bfh[4], bfl[4];
                ldsm4t(bfh, sBh + o);
                ldsm4t(bfl, sBl + o);
                mma16816(acc[nt2 * 2],     afh, bfh);
                mma16816(acc[nt2 * 2 + 1], afh, bfh + 2);
                mma16816(acc[nt2 * 2],     afh, bfl);
                mma16816(acc[nt2 * 2 + 1], afh, bfl + 2);
                mma16816(acc[nt2 * 2],     afl, bfh);
                mma16816(acc[nt2 * 2 + 1], afl, bfh + 2);
            }
        }
    }

    // epilogue: fused softmax over each 64-wide segment (2 per tile).
    // thread owns rows r, r+8; per row 2 cols in each of 16 n-tiles.
    const int rloc = wid * 16 + (lane >> 2);
#pragma unroll
    for (int h = 0; h < 2; h++) {            // row half: acc[..][2h],[2h+1]
        const int r = rloc + h * 8;
        float* orow = Out + ((size_t)b * C_ + row0 + r) * N_ + col0;
#pragma unroll
        for (int seg = 0; seg < 2; seg++) {
            float v[16];
#pragma unroll
            for (int j = 0; j < 8; j++) {
                v[2 * j]     = acc[seg * 8 + j][2 * h];
                v[2 * j + 1] = acc[seg * 8 + j][2 * h + 1];
            }
            float m = v[0];
#pragma unroll
            for (int j = 1; j < 16; j++) m = fmaxf(m, v[j]);
            m = fmaxf(m, __shfl_xor_sync(0xffffffffu, m, 1));
            m = fmaxf(m, __shfl_xor_sync(0xffffffffu, m, 2));
            float s = 0.f;
#pragma unroll
            for (int j = 0; j < 16; j++) { v[j] = __expf(v[j] - m); s += v[j]; }
            s += __shfl_xor_sync(0xffffffffu, s, 1);
            s += __shfl_xor_sync(0xffffffffu, s, 2);
            const float inv = 1.f / s;
#pragma unroll
            for (int j = 0; j < 8; j++) {
                float* p = orow + seg * 64 + j * 8 + (lane & 3) * 2;
                *(float2*)p = make_float2(v[2 * j] * inv, v[2 * j + 1] * inv);
            }
        }
    }
}

// ---------------------------------------------------------------------------
extern "C" void kernel_launch(void* const* d_in, const int* in_sizes, int n_in,
                              void* d_out, int out_size)
{
    const float* x_training = (const float*)d_in[0];  // KV
    const float* x_pre      = (const float*)d_in[1];  // Q
    float* out = (float*)d_out;

    cudaFuncSetAttribute(gemm1_kernel, cudaFuncAttributeMaxDynamicSharedMemorySize, SMEM_SZ);
    cudaFuncSetAttribute(gemm2_kernel, cudaFuncAttributeMaxDynamicSharedMemorySize, SMEM_SZ);

    __half *qh, *ql, *kh, *kl;
    cudaGetSymbolAddress((void**)&qh, g_qh);
    cudaGetSymbolAddress((void**)&ql, g_ql);
    cudaGetSymbolAddress((void**)&kh, g_kh);
    cudaGetSymbolAddress((void**)&kl, g_kl);

    const int nvec = B_ * C_ * N_ / 4;    // float4s per tensor

    // 1) fp16 hi/lo splits (KV split serves both GEMMs)
    split_kernel<<<nvec / 256, 256>>>(x_pre, qh, ql);
    split_kernel<<<nvec / 256, 256>>>(x_training, kh, kl);
    // 2) energy = Q @ KV^T   (HMMA, fp16-split 3-product)
    gemm1_kernel<<<dim3(C_ / 128, C_ / 128, B_), 256, SMEM_SZ>>>(qh, ql, kh, kl);
    // 3) attention = softmax(min - energy), split to fp16 hi/lo
    softmax512_split_kernel<<<B_ * C_, 128>>>();
    // 4) out = softmax64(attention @ KV)   (HMMA + fused final softmax)
    gemm2_kernel<<<dim3(N_ / 128, C_ / 128, B_), 256, SMEM_SZ>>>(kh, kl, out);
}

// round 5
// speedup vs baseline: 3.0836x; 1.1776x over previous
#include <cuda_runtime.h>
#include <cuda_fp16.h>
#include <cstdint>

#define B_ 16
#define C_ 512
#define N_ 4096   // H*W
#define W_ 64

// ---------------- scratch (__device__ globals: allocation-free rule) --------
__device__ __half g_qh[(size_t)B_ * C_ * N_];   // 67 MB each
__device__ __half g_ql[(size_t)B_ * C_ * N_];
__device__ __half g_kh[(size_t)B_ * C_ * N_];
__device__ __half g_kl[(size_t)B_ * C_ * N_];
__device__ __half g_ah[(size_t)B_ * C_ * C_];   // attention hi/lo, 8.4 MB each
__device__ __half g_al[(size_t)B_ * C_ * C_];
__device__ float  g_energy[(size_t)B_ * C_ * C_];

// ---------------- plain-target PTX helpers ----------------------------------
__device__ __forceinline__ uint32_t smem_u32(const void* p) {
    uint32_t a;
    asm("{ .reg .u64 t; cvta.to.shared.u64 t, %1; cvt.u32.u64 %0, t; }" : "=r"(a) : "l"(p));
    return a;
}
__device__ __forceinline__ void ldsm4(uint32_t* r, uint32_t addr) {
    asm volatile("ldmatrix.sync.aligned.m8n8.x4.shared.b16 {%0,%1,%2,%3}, [%4];"
                 : "=r"(r[0]), "=r"(r[1]), "=r"(r[2]), "=r"(r[3]) : "r"(addr));
}
__device__ __forceinline__ void ldsm4t(uint32_t* r, uint32_t addr) {
    asm volatile("ldmatrix.sync.aligned.m8n8.x4.trans.shared.b16 {%0,%1,%2,%3}, [%4];"
                 : "=r"(r[0]), "=r"(r[1]), "=r"(r[2]), "=r"(r[3]) : "r"(addr));
}
__device__ __forceinline__ void mma16816(float* d, const uint32_t* a, const uint32_t* b) {
    asm volatile(
        "mma.sync.aligned.m16n8k16.row.col.f32.f16.f16.f32 "
        "{%0,%1,%2,%3}, {%4,%5,%6,%7}, {%8,%9}, {%0,%1,%2,%3};"
        : "+f"(d[0]), "+f"(d[1]), "+f"(d[2]), "+f"(d[3])
        : "r"(a[0]), "r"(a[1]), "r"(a[2]), "r"(a[3]), "r"(b[0]), "r"(b[1]));
}
#define CP_ASYNC16(s, g) \
    asm volatile("cp.async.cg.shared.global [%0], [%1], 16;" :: "r"(s), "l"(g))
#define CP_COMMIT()  asm volatile("cp.async.commit_group;" ::: "memory")
#define CP_WAIT1()   asm volatile("cp.async.wait_group 1;" ::: "memory")

// Swizzled byte offsets inside an 8 KB tile.
// A-type tile: 128 rows x 32 halves (64 B/row); chunk = 16 B.
__device__ __forceinline__ uint32_t offA(int row, int ch) {
    return row * 64 + ((ch ^ ((row >> 1) & 3)) * 16);
}
// B-type tile (n-major): 32 rows x 128 halves (256 B/row).
__device__ __forceinline__ uint32_t offB(int krow, int ch) {
    return krow * 256 + ((ch ^ (krow & 7)) * 16);
}

static constexpr int STAGES   = 3;
static constexpr int STAGE_SZ = 32768;
static constexpr int SMEM_SZ  = STAGES * STAGE_SZ;   // 96 KB -> 2 CTAs/SM

// ---------------- prep: fp16 hi/lo split (both tensors, one launch) ---------
__global__ __launch_bounds__(256)
void split_all_kernel(const float* __restrict__ xq, const float* __restrict__ xk)
{
    const int which = blockIdx.y;          // 0 = Q, 1 = KV
    const float* x = which ? xk : xq;
    __half* hi = which ? g_kh : g_qh;
    __half* lo = which ? g_kl : g_ql;

    const size_t i = (size_t)blockIdx.x * 256 + threadIdx.x;
    const float4 v = ((const float4*)x)[i];
    const __half h0 = __float2half(v.x), h1 = __float2half(v.y);
    const __half h2 = __float2half(v.z), h3 = __float2half(v.w);
    const __half l0 = __float2half(v.x - __half2float(h0));
    const __half l1 = __float2half(v.y - __half2float(h1));
    const __half l2 = __float2half(v.z - __half2float(h2));
    const __half l3 = __float2half(v.w - __half2float(h3));
    ((__half2*)hi)[2 * i]     = __halves2half2(h0, h1);
    ((__half2*)hi)[2 * i + 1] = __halves2half2(h2, h3);
    ((__half2*)lo)[2 * i]     = __halves2half2(l0, l1);
    ((__half2*)lo)[2 * i + 1] = __halves2half2(l2, l3);
}

// ---------------- GEMM1 (NT): energy[c,d] = sum_n q[c,n] kv[d,n] -----------
// fp16 split operands, fp32 acc, 3 products (hh + hl + lh).
// 128x128 tile, BK=32, 3-stage cp.async pipeline, 2 CTAs/SM.
__global__ __launch_bounds__(256, 2)
void gemm1_kernel(const __half* __restrict__ Ah, const __half* __restrict__ Al,
                  const __half* __restrict__ Bh, const __half* __restrict__ Bl)
{
    extern __shared__ char smem[];
    const uint32_t sb = smem_u32(smem);
    const int tid = threadIdx.x, wid = tid >> 5, lane = tid & 31;
    const int b = blockIdx.z, row0 = blockIdx.y * 128, col0 = blockIdx.x * 128;
    const size_t bstr = (size_t)b * C_ * N_;

    const __half* srcs[4] = {
        Ah + bstr + (size_t)row0 * N_, Al + bstr + (size_t)row0 * N_,
        Bh + bstr + (size_t)col0 * N_, Bl + bstr + (size_t)col0 * N_ };

    auto load_stage = [&](int kb) {
        const uint32_t st = sb + (kb % STAGES) * STAGE_SZ;
#pragma unroll
        for (int t = 0; t < 4; t++) {
            const __half* src = srcs[t] + kb * 32;
            const uint32_t tb = st + t * 8192;
#pragma unroll
            for (int i = 0; i < 2; i++) {
                const int idx = tid + i * 256;
                const int row = idx >> 2, ch = idx & 3;
                CP_ASYNC16(tb + offA(row, ch), src + (size_t)row * N_ + ch * 8);
            }
        }
    };

    float acc[4][4][4];
#pragma unroll
    for (int i = 0; i < 4; i++)
#pragma unroll
        for (int j = 0; j < 4; j++)
#pragma unroll
            for (int k = 0; k < 4; k++) acc[i][j][k] = 0.f;

    load_stage(0); CP_COMMIT();
    load_stage(1); CP_COMMIT();

    const int wm = wid >> 2, wn = wid & 3;
    constexpr int NKB = N_ / 32;   // 128

    for (int kb = 0; kb < NKB; kb++) {
        CP_WAIT1();
        __syncthreads();
        if (kb + 2 < NKB) load_stage(kb + 2);
        CP_COMMIT();
        const uint32_t sAh = sb + (kb % STAGES) * STAGE_SZ;
        const uint32_t sAl = sAh + 8192, sBh = sAh + 16384, sBl = sAh + 24576;
#pragma unroll
        for (int ks = 0; ks < 2; ks++) {
            uint32_t afh[4][4], afl[4][4];
            {
                const int rb = wm * 64 + (lane & 7) + ((lane >> 3) & 1) * 8;
                const int ch = ks * 2 + (lane >> 4);
#pragma unroll
                for (int mt = 0; mt < 4; mt++) {
                    const uint32_t o = offA(rb + mt * 16, ch);
                    ldsm4(afh[mt], sAh + o);
                    ldsm4(afl[mt], sAl + o);
                }
            }
#pragma unroll
            for (int nt2 = 0; nt2 < 2; nt2++) {
                const int rb = wn * 32 + nt2 * 16 + (lane & 7) + ((lane >> 4) & 1) * 8;
                const int ch = ks * 2 + ((lane >> 3) & 1);
                const uint32_t o = offA(rb, ch);
                uint32_t bfh[4], bfl[4];
                ldsm4(bfh, sBh + o);
                ldsm4(bfl, sBl + o);
#pragma unroll
                for (int mt = 0; mt < 4; mt++) {
                    mma16816(acc[mt][nt2 * 2],     afh[mt], bfh);
                    mma16816(acc[mt][nt2 * 2 + 1], afh[mt], bfh + 2);
                    mma16816(acc[mt][nt2 * 2],     afh[mt], bfl);
                    mma16816(acc[mt][nt2 * 2 + 1], afh[mt], bfl + 2);
                    mma16816(acc[mt][nt2 * 2],     afl[mt], bfh);
                    mma16816(acc[mt][nt2 * 2 + 1], afl[mt], bfh + 2);
                }
            }
        }
    }

    // epilogue: plain fp32 store to g_energy
    float* Cm = g_energy + (size_t)b * C_ * C_;
    const int r0 = row0 + wm * 64 + (lane >> 2);
    const int c0g = col0 + wn * 32 + (lane & 3) * 2;
#pragma unroll
    for (int mt = 0; mt < 4; mt++)
#pragma unroll
        for (int nt = 0; nt < 4; nt++) {
            float* p = Cm + (size_t)(r0 + mt * 16) * C_ + c0g + nt * 8;
            *(float2*)p = make_float2(acc[mt][nt][0], acc[mt][nt][1]);
            *(float2*)(p + 8 * C_) = make_float2(acc[mt][nt][2], acc[mt][nt][3]);
        }
}

// ---------------- softmax over 512 + fp16 split of attention ---------------
__global__ __launch_bounds__(128)
void softmax512_split_kernel()
{
    __shared__ float red[4];
    const size_t row = blockIdx.x;
    const float* e = g_energy + row * C_;
    const int t = threadIdx.x;

    float4 v = ((const float4*)e)[t];
    float mn = fminf(fminf(v.x, v.y), fminf(v.z, v.w));
#pragma unroll
    for (int o = 16; o; o >>= 1) mn = fminf(mn, __shfl_xor_sync(0xffffffffu, mn, o));
    if ((t & 31) == 0) red[t >> 5] = mn;
    __syncthreads();
    mn = fminf(fminf(red[0], red[1]), fminf(red[2], red[3]));

    float4 w;
    w.x = __expf(mn - v.x); w.y = __expf(mn - v.y);
    w.z = __expf(mn - v.z); w.w = __expf(mn - v.w);
    float s = (w.x + w.y) + (w.z + w.w);
#pragma unroll
    for (int o = 16; o; o >>= 1) s += __shfl_xor_sync(0xffffffffu, s, o);
    __syncthreads();
    if ((t & 31) == 0) red[t >> 5] = s;
    __syncthreads();
    const float inv = 1.f / (red[0] + red[1] + red[2] + red[3]);
    w.x *= inv; w.y *= inv; w.z *= inv; w.w *= inv;

    const __half h0 = __float2half(w.x), h1 = __float2half(w.y);
    const __half h2 = __float2half(w.z), h3 = __float2half(w.w);
    const __half l0 = __float2half(w.x - __half2float(h0));
    const __half l1 = __float2half(w.y - __half2float(h1));
    const __half l2 = __float2half(w.z - __half2float(h2));
    const __half l3 = __float2half(w.w - __half2float(h3));
    __half2* ah = (__half2*)(g_ah + row * C_);
    __half2* al = (__half2*)(g_al + row * C_);
    ah[2 * t]     = __halves2half2(h0, h1);
    ah[2 * t + 1] = __halves2half2(h2, h3);
    al[2 * t]     = __halves2half2(l0, l1);
    al[2 * t + 1] = __halves2half2(l2, l3);
}

// ---------------- GEMM2 (NN): out[c,n] = softmax64( sum_d att[c,d] kv[d,n] )
// A = attention [C,C] (k contig), B = kv [C,N] (n contig, trans-ldmatrix).
// 128x128 tile, BK=32, warps 8x1 (16 rows x 128 cols each), fused softmax.
__global__ __launch_bounds__(256, 2)
void gemm2_kernel(const __half* __restrict__ Bh, const __half* __restrict__ Bl,
                  float* __restrict__ Out)
{
    extern __shared__ char smem[];
    const uint32_t sb = smem_u32(smem);
    const int tid = threadIdx.x, wid = tid >> 5, lane = tid & 31;
    const int b = blockIdx.z, row0 = blockIdx.y * 128, col0 = blockIdx.x * 128;

    const __half* aSrcs[2] = {
        g_ah + (size_t)b * C_ * C_ + (size_t)row0 * C_,
        g_al + (size_t)b * C_ * C_ + (size_t)row0 * C_ };
    const __half* bSrcs[2] = {
        Bh + (size_t)b * C_ * N_ + col0,
        Bl + (size_t)b * C_ * N_ + col0 };

    auto load_stage = [&](int kb) {
        const uint32_t st = sb + (kb % STAGES) * STAGE_SZ;
#pragma unroll
        for (int t = 0; t < 2; t++) {         // A tiles (A-type layout)
            const __half* src = aSrcs[t] + kb * 32;
            const uint32_t tb = st + t * 8192;
#pragma unroll
            for (int i = 0; i < 2; i++) {
                const int idx = tid + i * 256;
                const int row = idx >> 2, ch = idx & 3;
                CP_ASYNC16(tb + offA(row, ch), src + (size_t)row * C_ + ch * 8);
            }
        }
#pragma unroll
        for (int t = 0; t < 2; t++) {         // B tiles (n-major layout)
            const __half* src = bSrcs[t] + (size_t)(kb * 32) * N_;
            const uint32_t tb = st + 16384 + t * 8192;
#pragma unroll
            for (int i = 0; i < 2; i++) {
                const int idx = tid + i * 256;
                const int krow = idx >> 4, ch = idx & 15;
                CP_ASYNC16(tb + offB(krow, ch), src + (size_t)krow * N_ + ch * 8);
            }
        }
    };

    float acc[16][4];
#pragma unroll
    for (int i = 0; i < 16; i++)
#pragma unroll
        for (int k = 0; k < 4; k++) acc[i][k] = 0.f;

    load_stage(0); CP_COMMIT();
    load_stage(1); CP_COMMIT();

    constexpr int NKB = C_ / 32;   // 16

    for (int kb = 0; kb < NKB; kb++) {
        CP_WAIT1();
        __syncthreads();
        if (kb + 2 < NKB) load_stage(kb + 2);
        CP_COMMIT();
        const uint32_t sAh = sb + (kb % STAGES) * STAGE_SZ;
        const uint32_t sAl = sAh + 8192, sBh = sAh + 16384, sBl = sAh + 24576;
#pragma unroll
        for (int ks = 0; ks < 2; ks++) {
            uint32_t afh[4], afl[4];
            {
                const int row = wid * 16 + (lane & 7) + ((lane >> 3) & 1) * 8;
                const int ch = ks * 2 + (lane >> 4);
                const uint32_t o = offA(row, ch);
                ldsm4(afh, sAh + o);
                ldsm4(afl, sAl + o);
            }
            const int krow = ks * 16 + (lane & 7) + ((lane >> 3) & 1) * 8;
#pragma unroll
            for (int nt2 = 0; nt2 < 8; nt2++) {
                const int ch = nt2 * 2 + (lane >> 4);
                const uint32_t o = offB(krow, ch);
                uint32_t bfh[4], bfl[4];
                ldsm4t(bfh, sBh + o);
                ldsm4t(bfl, sBl + o);
                mma16816(acc[nt2 * 2],     afh, bfh);
                mma16816(acc[nt2 * 2 + 1], afh, bfh + 2);
                mma16816(acc[nt2 * 2],     afh, bfl);
                mma16816(acc[nt2 * 2 + 1], afh, bfl + 2);
                mma16816(acc[nt2 * 2],     afl, bfh);
                mma16816(acc[nt2 * 2 + 1], afl, bfh + 2);
            }
        }
    }

    // epilogue: fused softmax over each 64-wide segment (2 per tile).
    // thread owns rows r, r+8; per row 2 cols in each of 16 n-tiles.
    const int rloc = wid * 16 + (lane >> 2);
#pragma unroll
    for (int h = 0; h < 2; h++) {            // row half: acc[..][2h],[2h+1]
        const int r = rloc + h * 8;
        float* orow = Out + ((size_t)b * C_ + row0 + r) * N_ + col0;
#pragma unroll
        for (int seg = 0; seg < 2; seg++) {
            float v[16];
#pragma unroll
            for (int j = 0; j < 8; j++) {
                v[2 * j]     = acc[seg * 8 + j][2 * h];
                v[2 * j + 1] = acc[seg * 8 + j][2 * h + 1];
            }
            float m = v[0];
#pragma unroll
            for (int j = 1; j < 16; j++) m = fmaxf(m, v[j]);
            m = fmaxf(m, __shfl_xor_sync(0xffffffffu, m, 1));
            m = fmaxf(m, __shfl_xor_sync(0xffffffffu, m, 2));
            float s = 0.f;
#pragma unroll
            for (int j = 0; j < 16; j++) { v[j] = __expf(v[j] - m); s += v[j]; }
            s += __shfl_xor_sync(0xffffffffu, s, 1);
            s += __shfl_xor_sync(0xffffffffu, s, 2);
            const float inv = 1.f / s;
#pragma unroll
            for (int j = 0; j < 8; j++) {
                float* p = orow + seg * 64 + j * 8 + (lane & 3) * 2;
                *(float2*)p = make_float2(v[2 * j] * inv, v[2 * j + 1] * inv);
            }
        }
    }
}

// ---------------------------------------------------------------------------
extern "C" void kernel_launch(void* const* d_in, const int* in_sizes, int n_in,
                              void* d_out, int out_size)
{
    const float* x_training = (const float*)d_in[0];  // KV
    const float* x_pre      = (const float*)d_in[1];  // Q
    float* out = (float*)d_out;

    cudaFuncSetAttribute(gemm1_kernel, cudaFuncAttributeMaxDynamicSharedMemorySize, SMEM_SZ);
    cudaFuncSetAttribute(gemm2_kernel, cudaFuncAttributeMaxDynamicSharedMemorySize, SMEM_SZ);

    __half *qh, *ql, *kh, *kl;
    cudaGetSymbolAddress((void**)&qh, g_qh);
    cudaGetSymbolAddress((void**)&ql, g_ql);
    cudaGetSymbolAddress((void**)&kh, g_kh);
    cudaGetSymbolAddress((void**)&kl, g_kl);

    const int nvec = B_ * C_ * N_ / 4;    // float4s per tensor

    // 1) fp16 hi/lo splits of Q and KV, single launch (4 launches/call total
    //    -> ncu -s 5 -c 1 lands on replay-2's gemm1)
    split_all_kernel<<<dim3(nvec / 256, 2), 256>>>(x_pre, x_training);
    // 2) energy = Q @ KV^T   (HMMA, fp16-split 3-product)
    gemm1_kernel<<<dim3(C_ / 128, C_ / 128, B_), 256, SMEM_SZ>>>(qh, ql, kh, kl);
    // 3) attention = softmax(min - energy), split to fp16 hi/lo
    softmax512_split_kernel<<<B_ * C_, 128>>>();
    // 4) out = softmax64(attention @ KV)   (HMMA + fused final softmax)
    gemm2_kernel<<<dim3(N_ / 128, C_ / 128, B_), 256, SMEM_SZ>>>(kh, kl, out);
}

// round 6
// speedup vs baseline: 3.5623x; 1.1553x over previous
#include <cuda_runtime.h>
#include <cuda_fp16.h>
#include <cstdint>

#define B_ 16
#define C_ 512
#define N_ 4096   // H*W
#define W_ 64

// ---------------- scratch (__device__ globals: allocation-free rule) --------
__device__ __half g_qh[(size_t)B_ * C_ * N_];   // 67 MB each
__device__ __half g_ql[(size_t)B_ * C_ * N_];
__device__ __half g_kh[(size_t)B_ * C_ * N_];
__device__ __half g_kl[(size_t)B_ * C_ * N_];
__device__ __half g_ah[(size_t)B_ * C_ * C_];   // attention (fp16 hi only)
__device__ float  g_energy[(size_t)B_ * C_ * C_];

// ---------------- plain-target PTX helpers ----------------------------------
__device__ __forceinline__ uint32_t smem_u32(const void* p) {
    uint32_t a;
    asm("{ .reg .u64 t; cvta.to.shared.u64 t, %1; cvt.u32.u64 %0, t; }" : "=r"(a) : "l"(p));
    return a;
}
__device__ __forceinline__ void ldsm4(uint32_t* r, uint32_t addr) {
    asm volatile("ldmatrix.sync.aligned.m8n8.x4.shared.b16 {%0,%1,%2,%3}, [%4];"
                 : "=r"(r[0]), "=r"(r[1]), "=r"(r[2]), "=r"(r[3]) : "r"(addr));
}
__device__ __forceinline__ void ldsm4t(uint32_t* r, uint32_t addr) {
    asm volatile("ldmatrix.sync.aligned.m8n8.x4.trans.shared.b16 {%0,%1,%2,%3}, [%4];"
                 : "=r"(r[0]), "=r"(r[1]), "=r"(r[2]), "=r"(r[3]) : "r"(addr));
}
__device__ __forceinline__ void mma16816(float* d, const uint32_t* a, const uint32_t* b) {
    asm volatile(
        "mma.sync.aligned.m16n8k16.row.col.f32.f16.f16.f32 "
        "{%0,%1,%2,%3}, {%4,%5,%6,%7}, {%8,%9}, {%0,%1,%2,%3};"
        : "+f"(d[0]), "+f"(d[1]), "+f"(d[2]), "+f"(d[3])
        : "r"(a[0]), "r"(a[1]), "r"(a[2]), "r"(a[3]), "r"(b[0]), "r"(b[1]));
}
#define CP_ASYNC16(s, g) \
    asm volatile("cp.async.cg.shared.global [%0], [%1], 16;" :: "r"(s), "l"(g))
#define CP_COMMIT()  asm volatile("cp.async.commit_group;" ::: "memory")
#define CP_WAIT1()   asm volatile("cp.async.wait_group 1;" ::: "memory")

// Swizzled byte offsets inside an 8 KB tile.
// A-type tile: 128 rows x 32 halves (64 B/row); chunk = 16 B.
__device__ __forceinline__ uint32_t offA(int row, int ch) {
    return row * 64 + ((ch ^ ((row >> 1) & 3)) * 16);
}
// B-type tile (n-major): 32 rows x 128 halves (256 B/row).
__device__ __forceinline__ uint32_t offB(int krow, int ch) {
    return krow * 256 + ((ch ^ (krow & 7)) * 16);
}

static constexpr int STAGES = 3;
// gemm1: 4 tiles x 8 KB; gemm2: 3 tiles x 8 KB
static constexpr int STAGE1_SZ = 32768;
static constexpr int SMEM1_SZ  = STAGES * STAGE1_SZ;   // 96 KB
static constexpr int STAGE2_SZ = 24576;
static constexpr int SMEM2_SZ  = STAGES * STAGE2_SZ;   // 72 KB

// ---------------- prep: fp16 hi/lo split (both tensors, one launch) ---------
__global__ __launch_bounds__(256)
void split_all_kernel(const float* __restrict__ xq, const float* __restrict__ xk)
{
    const int which = blockIdx.y;          // 0 = Q, 1 = KV
    const float* x = which ? xk : xq;
    __half* hi = which ? g_kh : g_qh;
    __half* lo = which ? g_kl : g_ql;

    const size_t i = (size_t)blockIdx.x * 256 + threadIdx.x;
    const float4 v = ((const float4*)x)[i];
    const __half h0 = __float2half(v.x), h1 = __float2half(v.y);
    const __half h2 = __float2half(v.z), h3 = __float2half(v.w);
    const __half l0 = __float2half(v.x - __half2float(h0));
    const __half l1 = __float2half(v.y - __half2float(h1));
    const __half l2 = __float2half(v.z - __half2float(h2));
    const __half l3 = __float2half(v.w - __half2float(h3));
    ((__half2*)hi)[2 * i]     = __halves2half2(h0, h1);
    ((__half2*)hi)[2 * i + 1] = __halves2half2(h2, h3);
    ((__half2*)lo)[2 * i]     = __halves2half2(l0, l1);
    ((__half2*)lo)[2 * i + 1] = __halves2half2(l2, l3);
}

// ---------------- GEMM1 (NT): energy[c,d] = sum_n q[c,n] kv[d,n] -----------
// fp16 split operands, fp32 acc, 3 products (hh + hl + lh).
// 128x128 tile, BK=32, 3-stage cp.async pipeline, 2 CTAs/SM.
__global__ __launch_bounds__(256, 2)
void gemm1_kernel(const __half* __restrict__ Ah, const __half* __restrict__ Al,
                  const __half* __restrict__ Bh, const __half* __restrict__ Bl)
{
    extern __shared__ char smem[];
    const uint32_t sb = smem_u32(smem);
    const int tid = threadIdx.x, wid = tid >> 5, lane = tid & 31;
    const int b = blockIdx.z, row0 = blockIdx.y * 128, col0 = blockIdx.x * 128;
    const size_t bstr = (size_t)b * C_ * N_;

    const __half* srcs[4] = {
        Ah + bstr + (size_t)row0 * N_, Al + bstr + (size_t)row0 * N_,
        Bh + bstr + (size_t)col0 * N_, Bl + bstr + (size_t)col0 * N_ };

    auto load_stage = [&](int kb) {
        const uint32_t st = sb + (kb % STAGES) * STAGE1_SZ;
#pragma unroll
        for (int t = 0; t < 4; t++) {
            const __half* src = srcs[t] + kb * 32;
            const uint32_t tb = st + t * 8192;
#pragma unroll
            for (int i = 0; i < 2; i++) {
                const int idx = tid + i * 256;
                const int row = idx >> 2, ch = idx & 3;
                CP_ASYNC16(tb + offA(row, ch), src + (size_t)row * N_ + ch * 8);
            }
        }
    };

    float acc[4][4][4];
#pragma unroll
    for (int i = 0; i < 4; i++)
#pragma unroll
        for (int j = 0; j < 4; j++)
#pragma unroll
            for (int k = 0; k < 4; k++) acc[i][j][k] = 0.f;

    load_stage(0); CP_COMMIT();
    load_stage(1); CP_COMMIT();

    const int wm = wid >> 2, wn = wid & 3;
    constexpr int NKB = N_ / 32;   // 128

    for (int kb = 0; kb < NKB; kb++) {
        CP_WAIT1();
        __syncthreads();
        if (kb + 2 < NKB) load_stage(kb + 2);
        CP_COMMIT();
        const uint32_t sAh = sb + (kb % STAGES) * STAGE1_SZ;
        const uint32_t sAl = sAh + 8192, sBh = sAh + 16384, sBl = sAh + 24576;
#pragma unroll
        for (int ks = 0; ks < 2; ks++) {
            uint32_t afh[4][4], afl[4][4];
            {
                const int rb = wm * 64 + (lane & 7) + ((lane >> 3) & 1) * 8;
                const int ch = ks * 2 + (lane >> 4);
#pragma unroll
                for (int mt = 0; mt < 4; mt++) {
                    const uint32_t o = offA(rb + mt * 16, ch);
                    ldsm4(afh[mt], sAh + o);
                    ldsm4(afl[mt], sAl + o);
                }
            }
#pragma unroll
            for (int nt2 = 0; nt2 < 2; nt2++) {
                const int rb = wn * 32 + nt2 * 16 + (lane & 7) + ((lane >> 4) & 1) * 8;
                const int ch = ks * 2 + ((lane >> 3) & 1);
                const uint32_t o = offA(rb, ch);
                uint32_t bfh[4], bfl[4];
                ldsm4(bfh, sBh + o);
                ldsm4(bfl, sBl + o);
#pragma unroll
                for (int mt = 0; mt < 4; mt++) {
                    mma16816(acc[mt][nt2 * 2],     afh[mt], bfh);
                    mma16816(acc[mt][nt2 * 2 + 1], afh[mt], bfh + 2);
                    mma16816(acc[mt][nt2 * 2],     afh[mt], bfl);
                    mma16816(acc[mt][nt2 * 2 + 1], afh[mt], bfl + 2);
                    mma16816(acc[mt][nt2 * 2],     afl[mt], bfh);
                    mma16816(acc[mt][nt2 * 2 + 1], afl[mt], bfh + 2);
                }
            }
        }
    }

    // epilogue: plain fp32 store to g_energy
    float* Cm = g_energy + (size_t)b * C_ * C_;
    const int r0 = row0 + wm * 64 + (lane >> 2);
    const int c0g = col0 + wn * 32 + (lane & 3) * 2;
#pragma unroll
    for (int mt = 0; mt < 4; mt++)
#pragma unroll
        for (int nt = 0; nt < 4; nt++) {
            float* p = Cm + (size_t)(r0 + mt * 16) * C_ + c0g + nt * 8;
            *(float2*)p = make_float2(acc[mt][nt][0], acc[mt][nt][1]);
            *(float2*)(p + 8 * C_) = make_float2(acc[mt][nt][2], acc[mt][nt][3]);
        }
}

// ---------------- softmax over 512 -> fp16 attention -----------------------
__global__ __launch_bounds__(128)
void softmax512_split_kernel()
{
    __shared__ float red[4];
    const size_t row = blockIdx.x;
    const float* e = g_energy + row * C_;
    const int t = threadIdx.x;

    float4 v = ((const float4*)e)[t];
    float mn = fminf(fminf(v.x, v.y), fminf(v.z, v.w));
#pragma unroll
    for (int o = 16; o; o >>= 1) mn = fminf(mn, __shfl_xor_sync(0xffffffffu, mn, o));
    if ((t & 31) == 0) red[t >> 5] = mn;
    __syncthreads();
    mn = fminf(fminf(red[0], red[1]), fminf(red[2], red[3]));

    float4 w;
    w.x = __expf(mn - v.x); w.y = __expf(mn - v.y);
    w.z = __expf(mn - v.z); w.w = __expf(mn - v.w);
    float s = (w.x + w.y) + (w.z + w.w);
#pragma unroll
    for (int o = 16; o; o >>= 1) s += __shfl_xor_sync(0xffffffffu, s, o);
    __syncthreads();
    if ((t & 31) == 0) red[t >> 5] = s;
    __syncthreads();
    const float inv = 1.f / (red[0] + red[1] + red[2] + red[3]);

    __half2* ah = (__half2*)(g_ah + row * C_);
    ah[2 * t]     = __halves2half2(__float2half(w.x * inv), __float2half(w.y * inv));
    ah[2 * t + 1] = __halves2half2(__float2half(w.z * inv), __float2half(w.w * inv));
}

// ---------------- GEMM2 (NN): out[c,n] = softmax64( sum_d att[c,d] kv[d,n] )
// A = attention fp16 [C,C] (k contig), B = kv hi/lo [C,N] (trans-ldmatrix).
// Products: Ah*Bh + Ah*Bl. 128x128 tile, BK=32, warps 4x2 (32 rows x 64 cols),
// fused per-64-segment softmax epilogue.
__global__ __launch_bounds__(256, 2)
void gemm2_kernel(const __half* __restrict__ Bh, const __half* __restrict__ Bl,
                  float* __restrict__ Out)
{
    extern __shared__ char smem[];
    const uint32_t sb = smem_u32(smem);
    const int tid = threadIdx.x, wid = tid >> 5, lane = tid & 31;
    const int b = blockIdx.z, row0 = blockIdx.y * 128, col0 = blockIdx.x * 128;

    const __half* aSrc = g_ah + (size_t)b * C_ * C_ + (size_t)row0 * C_;
    const __half* bSrcs[2] = {
        Bh + (size_t)b * C_ * N_ + col0,
        Bl + (size_t)b * C_ * N_ + col0 };

    auto load_stage = [&](int kb) {
        const uint32_t st = sb + (kb % STAGES) * STAGE2_SZ;
        {   // A tile (fp16 attention, A-type layout)
            const __half* src = aSrc + kb * 32;
#pragma unroll
            for (int i = 0; i < 2; i++) {
                const int idx = tid + i * 256;
                const int row = idx >> 2, ch = idx & 3;
                CP_ASYNC16(st + offA(row, ch), src + (size_t)row * C_ + ch * 8);
            }
        }
#pragma unroll
        for (int t = 0; t < 2; t++) {         // B tiles (n-major layout)
            const __half* src = bSrcs[t] + (size_t)(kb * 32) * N_;
            const uint32_t tb = st + 8192 + t * 8192;
#pragma unroll
            for (int i = 0; i < 2; i++) {
                const int idx = tid + i * 256;
                const int krow = idx >> 4, ch = idx & 15;
                CP_ASYNC16(tb + offB(krow, ch), src + (size_t)krow * N_ + ch * 8);
            }
        }
    };

    float acc[2][8][4];
#pragma unroll
    for (int i = 0; i < 2; i++)
#pragma unroll
        for (int j = 0; j < 8; j++)
#pragma unroll
            for (int k = 0; k < 4; k++) acc[i][j][k] = 0.f;

    load_stage(0); CP_COMMIT();
    load_stage(1); CP_COMMIT();

    const int wm = wid >> 1, wn = wid & 1;    // 4 x 2 warps
    constexpr int NKB = C_ / 32;   // 16

    for (int kb = 0; kb < NKB; kb++) {
        CP_WAIT1();
        __syncthreads();
        if (kb + 2 < NKB) load_stage(kb + 2);
        CP_COMMIT();
        const uint32_t sA = sb + (kb % STAGES) * STAGE2_SZ;
        const uint32_t sBh = sA + 8192, sBl = sA + 16384;
#pragma unroll
        for (int ks = 0; ks < 2; ks++) {
            uint32_t afh[2][4];
            {
                const int rb = wm * 32 + (lane & 7) + ((lane >> 3) & 1) * 8;
                const int ch = ks * 2 + (lane >> 4);
#pragma unroll
                for (int mt = 0; mt < 2; mt++)
                    ldsm4(afh[mt], sA + offA(rb + mt * 16, ch));
            }
            const int krow = ks * 16 + (lane & 7) + ((lane >> 3) & 1) * 8;
#pragma unroll
            for (int nt2 = 0; nt2 < 4; nt2++) {
                const int ch = wn * 8 + nt2 * 2 + (lane >> 4);
                const uint32_t o = offB(krow, ch);
                uint32_t bfh[4], bfl[4];
                ldsm4t(bfh, sBh + o);
                ldsm4t(bfl, sBl + o);
#pragma unroll
                for (int mt = 0; mt < 2; mt++) {
                    mma16816(acc[mt][nt2 * 2],     afh[mt], bfh);
                    mma16816(acc[mt][nt2 * 2 + 1], afh[mt], bfh + 2);
                    mma16816(acc[mt][nt2 * 2],     afh[mt], bfl);
                    mma16816(acc[mt][nt2 * 2 + 1], afh[mt], bfl + 2);
                }
            }
        }
    }

    // epilogue: fused softmax over this warp's 64-col segment.
    // warp covers rows wm*32..+31, cols wn*64..+63 (one whole segment).
#pragma unroll
    for (int mt = 0; mt < 2; mt++)
#pragma unroll
    for (int h = 0; h < 2; h++) {
        const int r = wm * 32 + mt * 16 + (lane >> 2) + h * 8;
        float* orow = Out + ((size_t)b * C_ + row0 + r) * N_ + col0 + wn * 64;
        float v[16];
#pragma unroll
        for (int j = 0; j < 8; j++) {
            v[2 * j]     = acc[mt][j][2 * h];
            v[2 * j + 1] = acc[mt][j][2 * h + 1];
        }
        float m = v[0];
#pragma unroll
        for (int j = 1; j < 16; j++) m = fmaxf(m, v[j]);
        m = fmaxf(m, __shfl_xor_sync(0xffffffffu, m, 1));
        m = fmaxf(m, __shfl_xor_sync(0xffffffffu, m, 2));
        float s = 0.f;
#pragma unroll
        for (int j = 0; j < 16; j++) { v[j] = __expf(v[j] - m); s += v[j]; }
        s += __shfl_xor_sync(0xffffffffu, s, 1);
        s += __shfl_xor_sync(0xffffffffu, s, 2);
        const float inv = 1.f / s;
#pragma unroll
        for (int j = 0; j < 8; j++) {
            float* p = orow + j * 8 + (lane & 3) * 2;
            *(float2*)p = make_float2(v[2 * j] * inv, v[2 * j + 1] * inv);
        }
    }
}

// ---------------------------------------------------------------------------
extern "C" void kernel_launch(void* const* d_in, const int* in_sizes, int n_in,
                              void* d_out, int out_size)
{
    const float* x_training = (const float*)d_in[0];  // KV
    const float* x_pre      = (const float*)d_in[1];  // Q
    float* out = (float*)d_out;

    cudaFuncSetAttribute(gemm1_kernel, cudaFuncAttributeMaxDynamicSharedMemorySize, SMEM1_SZ);
    cudaFuncSetAttribute(gemm2_kernel, cudaFuncAttributeMaxDynamicSharedMemorySize, SMEM2_SZ);

    __half *qh, *ql, *kh, *kl;
    cudaGetSymbolAddress((void**)&qh, g_qh);
    cudaGetSymbolAddress((void**)&ql, g_ql);
    cudaGetSymbolAddress((void**)&kh, g_kh);
    cudaGetSymbolAddress((void**)&kl, g_kl);

    const int nvec = B_ * C_ * N_ / 4;    // float4s per tensor

    // 1) fp16 hi/lo splits of Q and KV
    split_all_kernel<<<dim3(nvec / 256, 2), 256>>>(x_pre, x_training);
    // 2) energy = Q @ KV^T   (HMMA, fp16-split 3-product)
    gemm1_kernel<<<dim3(C_ / 128, C_ / 128, B_), 256, SMEM1_SZ>>>(qh, ql, kh, kl);
    // 3) attention = softmax(min - energy) -> fp16
    softmax512_split_kernel<<<B_ * C_, 128>>>();
    // 4) out = softmax64(attention @ KV)   (HMMA 2-product + fused softmax)
    gemm2_kernel<<<dim3(N_ / 128, C_ / 128, B_), 256, SMEM2_SZ>>>(kh, kl, out);
}